// round 15
// baseline (speedup 1.0000x reference)
#include <cuda_runtime.h>
#include <cstdint>

// RevNet additive coupling: y1 = x1 ; y2 = x2 + x1 @ W
// x rows: [x1(128) | x2(128)] fp32, W: 128x128 fp32, 262144 rows.
//
// R15 = R14 (4x256 CTAs, reg-resident W frags, ldmatrix A, skewed x1/x2
// pipelines, wait_group-1 full-iteration cover) with the R14 RACE FIXED:
// the x2 cp.async stage is TRIPLE-buffered, so the buffer being read in
// this iteration's epilogue is only rewritten two iterations later —
// provably separated by an intervening barrier. One barrier per iteration.

#define D 128
#define TILE_M 16
#define THREADS 256
#define SA 68    // X tile (bf16-pair words) row stride
#define SB 136   // W2 staging (bf16-pair words) row stride

static constexpr int ROWS_TOTAL = 262144;
static constexpr int NUM_TILES  = ROWS_TOTAL / TILE_M;    // 16384
static constexpr int XB_WORDS   = TILE_M * SA;            // 1088 (4352 B)
static constexpr int W2_WORDS   = 64 * SB;                // 8704 (34816 B staging)
// Overlay: XB0 [0,4352) XB1 [4352,8704) X2S0/1/2 [8704, 8704+3*8192=33280)
static constexpr int X2S_OFF    = 2 * XB_WORDS * 4;       // 8704 (bytes)
static constexpr int X2S_BYTES  = TILE_M * D * 4;         // 8192 per buffer
static constexpr int SMEM_BYTES = W2_WORDS * 4;           // 34816 (covers overlay)

__device__ __forceinline__ uint32_t bfpack(float lo, float hi) {
    uint32_t r;
    asm("cvt.rn.bf16x2.f32 %0, %1, %2;" : "=r"(r) : "f"(hi), "f"(lo));
    return r;
}
__device__ __forceinline__ void mma_bf16(float& d0, float& d1, float& d2, float& d3,
                                         uint32_t a0, uint32_t a1, uint32_t a2, uint32_t a3,
                                         uint32_t b0, uint32_t b1) {
    asm volatile(
        "mma.sync.aligned.m16n8k16.row.col.f32.bf16.bf16.f32 "
        "{%0,%1,%2,%3}, {%4,%5,%6,%7}, {%8,%9}, {%0,%1,%2,%3};"
        : "+f"(d0), "+f"(d1), "+f"(d2), "+f"(d3)
        : "r"(a0), "r"(a1), "r"(a2), "r"(a3), "r"(b0), "r"(b1));
}
__device__ __forceinline__ void ldsm_x4(uint32_t& a0, uint32_t& a1,
                                        uint32_t& a2, uint32_t& a3, uint32_t addr) {
    asm volatile("ldmatrix.sync.aligned.m8n8.x4.shared.b16 {%0,%1,%2,%3}, [%4];"
                 : "=r"(a0), "=r"(a1), "=r"(a2), "=r"(a3) : "r"(addr));
}
__device__ __forceinline__ void cp16(uint32_t smem_dst, const void* gsrc) {
    asm volatile("cp.async.cg.shared.global [%0], [%1], 16;" :: "r"(smem_dst), "l"(gsrc));
}
// x2 stage chunk slot: chunk (r, q) -> 16*q + ((r + 4*(q&1)) & 15)
// Coalesced cp.async src and 2-phase (conflict-free) epilogue LDS.64.
__device__ __forceinline__ uint32_t x2slot(int r, int q) {
    return (uint32_t)((q << 4) + ((r + ((q & 1) << 2)) & 15));
}

__global__ void __launch_bounds__(THREADS, 4)
revnet_bf16_kernel(const float* __restrict__ x,
                   const float* __restrict__ w,
                   float* __restrict__ out)
{
    extern __shared__ uint32_t smem[];

    const int tid  = threadIdx.x;
    const int wid  = tid >> 5;
    const int lane = tid & 31;
    const int gid  = lane >> 2;          // 0..7
    const int tig  = lane & 3;           // 0..3
    const int nbase = wid << 4;          // n-group base (16 cols per warp)

    // --- Stage W2 into smem (bf16 k-pairs: row kp=k/2, col n), one-time. ---
    uint32_t* W2 = smem;
    for (int idx = tid; idx < 64 * D; idx += THREADS) {
        const int kp = idx >> 7, n = idx & 127;
        W2[kp * SB + n] = bfpack(w[(2 * kp) * D + n], w[(2 * kp + 1) * D + n]);
    }
    __syncthreads();

    // --- Consume W2 into persistent per-thread B fragments. ---
    uint32_t Breg[8][2][2];
    #pragma unroll
    for (int ks = 0; ks < 8; ks++) {
        #pragma unroll
        for (int j = 0; j < 2; j++) {
            Breg[ks][j][0] = W2[(8 * ks + tig) * SB + nbase + 8 * j + gid];
            Breg[ks][j][1] = W2[(8 * ks + 4 + tig) * SB + nbase + 8 * j + gid];
        }
    }
    __syncthreads();   // frag reads done -> smem region overlaid below

    uint32_t* XB[2] = { smem, smem + XB_WORDS };   // bf16 x1 tiles (overlay)
    const uint32_t smem_u = (uint32_t)__cvta_generic_to_shared(smem);
    const uint32_t x2s_u[3] = { smem_u + X2S_OFF,
                                smem_u + X2S_OFF + X2S_BYTES,
                                smem_u + X2S_OFF + 2 * X2S_BYTES };

    // ldmatrix per-lane base addresses (bytes) into each XB buffer.
    const uint32_t lrow = lane & 15;
    const uint32_t lkof = (lane >> 4) << 2;        // +4 words = +8 k
    const uint32_t ab0 = smem_u + (lrow * SA + lkof) * 4;
    const uint32_t ab1 = ab0 + XB_WORDS * 4;

    // Epilogue x2-stage read offsets (bytes, within a stage buffer).
    uint32_t x2rd[2][2];   // [j][mrow half: r=gid / r=gid+8]
    #pragma unroll
    for (int j = 0; j < 2; j++) {
        const int q = 4 * wid + 2 * j + (tig >> 1);
        x2rd[j][0] = x2slot(gid,     q) * 16 + ((tig & 1) << 3);
        x2rd[j][1] = x2slot(gid + 8, q) * 16 + ((tig & 1) << 3);
    }

    const int start   = blockIdx.x;
    const int gstride = gridDim.x;

    // ---- Preamble ----
    {
        const long rowbase = (long)start * TILE_M;
        #pragma unroll
        for (int p = 0; p < 2; p++) {
            const int  i = p * THREADS + tid;
            const int  r = i >> 5;
            const int  q = i & 31;
            const long g = (rowbase + r) * 256L + 4 * q;
            const float4 v = *(const float4*)(x + g);
            *(float4*)(out + g) = v;                      // y1 (exact fp32)
            XB[0][r * SA + 2 * q]     = bfpack(v.x, v.y);
            XB[0][r * SA + 2 * q + 1] = bfpack(v.z, v.w);
        }
        #pragma unroll
        for (int p = 0; p < 2; p++) {
            const int i = p * THREADS + tid;
            const int r = i >> 5;
            const int q = i & 31;
            cp16(x2s_u[0] + x2slot(r, q) * 16,
                 x + (rowbase + r) * 256L + 128 + 4 * q);   // x2(start) -> s0
        }
        asm volatile("cp.async.commit_group;");   // G(it 0)
    }
    float4 pf[2];
    if (start + gstride < NUM_TILES) {
        const long nb = (long)(start + gstride) * TILE_M;
        #pragma unroll
        for (int p = 0; p < 2; p++) {
            const int i = p * THREADS + tid;
            pf[p] = *(const float4*)(x + (nb + (i >> 5)) * 256L + 4 * (i & 31));
        }
    }
    __syncthreads();   // XB[0] visible (x2 stage covered by in-loop wait)

    int buf = 0;       // XB buffer parity
    int s   = 0;       // x2 stage index (iteration count mod 3)
    for (int t = start; t < NUM_TILES; t += gstride, buf ^= 1) {
        const long rowbase = (long)t * TILE_M;
        const int  t1 = t + gstride;
        const int  t2 = t1 + gstride;
        const bool h1 = t1 < NUM_TILES;
        const bool h2 = t2 < NUM_TILES;
        const int  s1 = (s == 2) ? 0 : s + 1;   // next stage buffer

        // (a) Drain pf (x1 of t1, loaded LAST iteration): y1 STG + STS.
        if (h1) {
            const long nb = (long)t1 * TILE_M;
            uint32_t* Xn = XB[buf ^ 1];
            #pragma unroll
            for (int p = 0; p < 2; p++) {
                const int  i = p * THREADS + tid;
                const int  r = i >> 5;
                const int  q = i & 31;
                *(float4*)(out + (nb + r) * 256L + 4 * q) = pf[p];   // y1
                Xn[r * SA + 2 * q]     = bfpack(pf[p].x, pf[p].y);
                Xn[r * SA + 2 * q + 1] = bfpack(pf[p].z, pf[p].w);
            }
        }

        // (b) Issue x1 LDG for t2; commit x2 cp.async group for t1 into s1.
        if (h2) {
            const long nb = (long)t2 * TILE_M;
            #pragma unroll
            for (int p = 0; p < 2; p++) {
                const int i = p * THREADS + tid;
                pf[p] = *(const float4*)(x + (nb + (i >> 5)) * 256L + 4 * (i & 31));
            }
        }
        if (h1) {
            const long nb = (long)t1 * TILE_M;
            const uint32_t dstb = x2s_u[s1];
            #pragma unroll
            for (int p = 0; p < 2; p++) {
                const int i = p * THREADS + tid;
                const int r = i >> 5;
                const int q = i & 31;
                cp16(dstb + x2slot(r, q) * 16,
                     x + (nb + r) * 256L + 128 + 4 * q);
            }
            asm volatile("cp.async.commit_group;");   // G(t1)
        }

        // (c) Mainloop on tile t: B in regs, A via ldmatrix from XB[buf].
        float acc[2][4];
        #pragma unroll
        for (int j = 0; j < 2; j++)
            { acc[j][0] = 0.f; acc[j][1] = 0.f; acc[j][2] = 0.f; acc[j][3] = 0.f; }

        const uint32_t ab = buf ? ab1 : ab0;
        #pragma unroll
        for (int ks = 0; ks < 8; ks++) {
            uint32_t a0, a1, a2, a3;
            ldsm_x4(a0, a1, a2, a3, ab + ks * 32);
            #pragma unroll
            for (int j = 0; j < 2; j++) {
                mma_bf16(acc[j][0], acc[j][1], acc[j][2], acc[j][3],
                         a0, a1, a2, a3, Breg[ks][j][0], Breg[ks][j][1]);
            }
        }

        // (c2) Drain G(t) — committed LAST iteration (full-iteration cover).
        //      G(t1), committed this iteration, stays in flight.
        if (h1) { asm volatile("cp.async.wait_group 1;"); }
        else    { asm volatile("cp.async.wait_group 0;"); }
        __syncthreads();   // x2(t) stage visible; XB handoffs ordered

        // (d) Epilogue: y2(t) = x2 + acc; x2 from stage s (2-phase LDS.64).
        //     Stage s is next rewritten in iteration t+2's (b), which lies
        //     beyond iteration t+1's barrier -> race-free with 3 buffers.
        const long r0 = rowbase + gid;
        const uint32_t srcb = x2s_u[s];
        #pragma unroll
        for (int j = 0; j < 2; j++) {
            float2 xv0, xv1;
            asm volatile("ld.shared.v2.f32 {%0,%1}, [%2];"
                         : "=f"(xv0.x), "=f"(xv0.y) : "r"(srcb + x2rd[j][0]));
            asm volatile("ld.shared.v2.f32 {%0,%1}, [%2];"
                         : "=f"(xv1.x), "=f"(xv1.y) : "r"(srcb + x2rd[j][1]));
            const long g0 = r0 * 256L + 128 + nbase + 8 * j + 2 * tig;
            float2 o0, o1;
            o0.x = xv0.x + acc[j][0];
            o0.y = xv0.y + acc[j][1];
            o1.x = xv1.x + acc[j][2];
            o1.y = xv1.y + acc[j][3];
            *(float2*)(out + g0) = o0;
            *(float2*)(out + g0 + 8 * 256L) = o1;
        }

        s = s1;
    }
}

extern "C" void kernel_launch(void* const* d_in, const int* in_sizes, int n_in,
                              void* d_out, int out_size)
{
    const float* x = (const float*)d_in[0];   // [8, 32768, 256] fp32
    const float* w = (const float*)d_in[1];   // [128, 128] fp32
    float* out = (float*)d_out;

    cudaFuncSetAttribute(revnet_bf16_kernel,
                         cudaFuncAttributeMaxDynamicSharedMemorySize,
                         SMEM_BYTES);

    // 4 CTAs per SM (occ 50%), full-iteration cover, triple-buffered x2 stage.
    revnet_bf16_kernel<<<592, THREADS, SMEM_BYTES>>>(x, w, out);
}

// round 16
// speedup vs baseline: 1.0496x; 1.0496x over previous
#include <cuda_runtime.h>
#include <cstdint>

// RevNet additive coupling: y1 = x1 ; y2 = x2 + x1 @ W
// x rows: [x1(128) | x2(128)] fp32, W: 128x128 fp32, 262144 rows.
//
// R16 = R12 (champion: 3x256 CTAs, reg-resident W frags, ldmatrix A,
// 1-iter-skewed x1/x2 pipelines) + COALESCED EPILOGUE: acc is staged to
// smem (padded), then a coalesced float4 pass computes y2 = D + x2 with
// x2 also loaded coalesced. Kills the 8-line-per-op scattered LDG.64/
// STG.64 wavefront waste that made R12 L1TEX-bound.

#define D 128
#define TILE_M 16
#define THREADS 256
#define SA 68    // X tile (bf16-pair words) row stride
#define SB 136   // W2 staging (bf16-pair words) row stride
#define PD 132   // D-stage row stride (floats)

static constexpr int ROWS_TOTAL = 262144;
static constexpr int NUM_TILES  = ROWS_TOTAL / TILE_M;    // 16384
static constexpr int XB_WORDS   = TILE_M * SA;            // 1088 (4352 B)
static constexpr int W2_WORDS   = 64 * SB;                // 8704 (34816 B staging)
// Overlay: XB0 [0,1088) XB1 [1088,2176) Dstage [2176, 2176+16*132=4288) words
static constexpr int D_OFF      = 2 * XB_WORDS;           // word offset
static constexpr int SMEM_BYTES = W2_WORDS * 4;           // 34816 (covers overlay)

__device__ __forceinline__ uint32_t bfpack(float lo, float hi) {
    uint32_t r;
    asm("cvt.rn.bf16x2.f32 %0, %1, %2;" : "=r"(r) : "f"(hi), "f"(lo));
    return r;
}
__device__ __forceinline__ void mma_bf16(float& d0, float& d1, float& d2, float& d3,
                                         uint32_t a0, uint32_t a1, uint32_t a2, uint32_t a3,
                                         uint32_t b0, uint32_t b1) {
    asm volatile(
        "mma.sync.aligned.m16n8k16.row.col.f32.bf16.bf16.f32 "
        "{%0,%1,%2,%3}, {%4,%5,%6,%7}, {%8,%9}, {%0,%1,%2,%3};"
        : "+f"(d0), "+f"(d1), "+f"(d2), "+f"(d3)
        : "r"(a0), "r"(a1), "r"(a2), "r"(a3), "r"(b0), "r"(b1));
}
__device__ __forceinline__ void ldsm_x4(uint32_t& a0, uint32_t& a1,
                                        uint32_t& a2, uint32_t& a3, uint32_t addr) {
    asm volatile("ldmatrix.sync.aligned.m8n8.x4.shared.b16 {%0,%1,%2,%3}, [%4];"
                 : "=r"(a0), "=r"(a1), "=r"(a2), "=r"(a3) : "r"(addr));
}

__global__ void __launch_bounds__(THREADS, 3)
revnet_bf16_kernel(const float* __restrict__ x,
                   const float* __restrict__ w,
                   float* __restrict__ out)
{
    extern __shared__ uint32_t smem[];

    const int tid  = threadIdx.x;
    const int wid  = tid >> 5;
    const int lane = tid & 31;
    const int gid  = lane >> 2;          // 0..7
    const int tig  = lane & 3;           // 0..3
    const int nbase = wid << 4;          // n-group base (16 cols per warp)

    // --- Stage W2 into smem (bf16 k-pairs: row kp=k/2, col n), one-time. ---
    uint32_t* W2 = smem;
    for (int idx = tid; idx < 64 * D; idx += THREADS) {
        const int kp = idx >> 7, n = idx & 127;
        W2[kp * SB + n] = bfpack(w[(2 * kp) * D + n], w[(2 * kp + 1) * D + n]);
    }
    __syncthreads();

    // --- Consume W2 into persistent per-thread B fragments. ---
    uint32_t Breg[8][2][2];
    #pragma unroll
    for (int ks = 0; ks < 8; ks++) {
        #pragma unroll
        for (int j = 0; j < 2; j++) {
            Breg[ks][j][0] = W2[(8 * ks + tig) * SB + nbase + 8 * j + gid];
            Breg[ks][j][1] = W2[(8 * ks + 4 + tig) * SB + nbase + 8 * j + gid];
        }
    }
    __syncthreads();   // frag reads done -> smem region overlaid below

    uint32_t* XB[2] = { smem, smem + XB_WORDS };   // bf16 x1 tiles (overlay)
    float*    Dsf   = (float*)(smem + D_OFF);      // D stage [16][PD] fp32

    // ldmatrix per-lane base addresses (bytes) into each XB buffer.
    const uint32_t smem_u = (uint32_t)__cvta_generic_to_shared(smem);
    const uint32_t lrow = lane & 15;
    const uint32_t lkof = (lane >> 4) << 2;        // +4 words = +8 k
    const uint32_t ab0 = smem_u + (lrow * SA + lkof) * 4;
    const uint32_t ab1 = ab0 + XB_WORDS * 4;

    const int start   = blockIdx.x;
    const int gstride = gridDim.x;

    // ---- Preamble: XB[0] <- x1(start) (+y1 STG); x2(start) coalesced regs;
    //      pf <- x1(start+gstride). ----
    {
        const long rowbase = (long)start * TILE_M;
        #pragma unroll
        for (int p = 0; p < 2; p++) {
            const int  i = p * THREADS + tid;
            const int  r = i >> 5;
            const int  q = i & 31;
            const long g = (rowbase + r) * 256L + 4 * q;
            const float4 v = *(const float4*)(x + g);
            *(float4*)(out + g) = v;                      // y1 (exact fp32)
            XB[0][r * SA + 2 * q]     = bfpack(v.x, v.y);
            XB[0][r * SA + 2 * q + 1] = bfpack(v.z, v.w);
        }
    }
    float4 x2r[2];
    {
        const long rowbase = (long)start * TILE_M;
        #pragma unroll
        for (int p = 0; p < 2; p++) {
            const int i = p * THREADS + tid;
            x2r[p] = *(const float4*)(x + (rowbase + (i >> 5)) * 256L + 128 + 4 * (i & 31));
        }
    }
    float4 pf[2];
    if (start + gstride < NUM_TILES) {
        const long nb = (long)(start + gstride) * TILE_M;
        #pragma unroll
        for (int p = 0; p < 2; p++) {
            const int i = p * THREADS + tid;
            pf[p] = *(const float4*)(x + (nb + (i >> 5)) * 256L + 4 * (i & 31));
        }
    }
    __syncthreads();

    int buf = 0;
    for (int t = start; t < NUM_TILES; t += gstride, buf ^= 1) {
        const long rowbase = (long)t * TILE_M;
        const int  t1 = t + gstride;
        const int  t2 = t1 + gstride;
        const bool h1 = t1 < NUM_TILES;
        const bool h2 = t2 < NUM_TILES;

        // (a) Drain pf (x1 of t1, loaded LAST iteration): y1 STG + STS.
        if (h1) {
            const long nb = (long)t1 * TILE_M;
            uint32_t* Xn = XB[buf ^ 1];
            #pragma unroll
            for (int p = 0; p < 2; p++) {
                const int  i = p * THREADS + tid;
                const int  r = i >> 5;
                const int  q = i & 31;
                *(float4*)(out + (nb + r) * 256L + 4 * q) = pf[p];   // y1
                Xn[r * SA + 2 * q]     = bfpack(pf[p].x, pf[p].y);
                Xn[r * SA + 2 * q + 1] = bfpack(pf[p].z, pf[p].w);
            }
        }

        // (b) Issue x1 LDG for t2 (full-iteration cover).
        if (h2) {
            const long nb = (long)t2 * TILE_M;
            #pragma unroll
            for (int p = 0; p < 2; p++) {
                const int i = p * THREADS + tid;
                pf[p] = *(const float4*)(x + (nb + (i >> 5)) * 256L + 4 * (i & 31));
            }
        }

        // (c) Mainloop on tile t: B in regs, A via ldmatrix from XB[buf].
        float acc[2][4];
        #pragma unroll
        for (int j = 0; j < 2; j++)
            { acc[j][0] = 0.f; acc[j][1] = 0.f; acc[j][2] = 0.f; acc[j][3] = 0.f; }

        const uint32_t ab = buf ? ab1 : ab0;
        #pragma unroll
        for (int ks = 0; ks < 8; ks++) {
            uint32_t a0, a1, a2, a3;
            ldsm_x4(a0, a1, a2, a3, ab + ks * 32);
            #pragma unroll
            for (int j = 0; j < 2; j++) {
                mma_bf16(acc[j][0], acc[j][1], acc[j][2], acc[j][3],
                         a0, a1, a2, a3, Breg[ks][j][0], Breg[ks][j][1]);
            }
        }

        // (c2) Stage acc -> Dsf (padded; float2 stores per fragment pair).
        #pragma unroll
        for (int j = 0; j < 2; j++) {
            const int c = nbase + 8 * j + 2 * tig;
            *(float2*)(Dsf + gid * PD + c)       = make_float2(acc[j][0], acc[j][1]);
            *(float2*)(Dsf + (gid + 8) * PD + c) = make_float2(acc[j][2], acc[j][3]);
        }
        __syncthreads();   // BARRIER A: D stage complete

        // (d) Coalesced epilogue: y2(t) = D + x2 (x2 loaded LAST iteration).
        #pragma unroll
        for (int p = 0; p < 2; p++) {
            const int  i = p * THREADS + tid;
            const int  r = i >> 5;
            const int  q = i & 31;
            const float4 dv = *(const float4*)(Dsf + r * PD + 4 * q);
            float4 o;
            o.x = dv.x + x2r[p].x;
            o.y = dv.y + x2r[p].y;
            o.z = dv.z + x2r[p].z;
            o.w = dv.w + x2r[p].w;
            *(float4*)(out + (rowbase + r) * 256L + 128 + 4 * q) = o;
        }

        // (e) Prefetch x2 of t1 coalesced (consumed next iteration).
        if (h1) {
            const long nb = (long)t1 * TILE_M;
            #pragma unroll
            for (int p = 0; p < 2; p++) {
                const int i = p * THREADS + tid;
                x2r[p] = *(const float4*)(x + (nb + (i >> 5)) * 256L + 128 + 4 * (i & 31));
            }
        }

        __syncthreads();   // BARRIER B: XB handoff + Dsf anti-dependency
    }
}

extern "C" void kernel_launch(void* const* d_in, const int* in_sizes, int n_in,
                              void* d_out, int out_size)
{
    const float* x = (const float*)d_in[0];   // [8, 32768, 256] fp32
    const float* w = (const float*)d_in[1];   // [128, 128] fp32
    float* out = (float*)d_out;

    cudaFuncSetAttribute(revnet_bf16_kernel,
                         cudaFuncAttributeMaxDynamicSharedMemorySize,
                         SMEM_BYTES);

    // 3 CTAs per SM, reg-resident W, coalesced epilogue through smem D-stage.
    revnet_bf16_kernel<<<444, THREADS, SMEM_BYTES>>>(x, w, out);
}